// round 3
// baseline (speedup 1.0000x reference)
#include <cuda_runtime.h>
#include <math.h>
#include <stdint.h>

#define DD 512
#define PP 36
#define NT 1024
#define NWARP 32
#define EPSN 1e-12f
#define SCALE_CLS 7.0f
#define TILE_F (PP*DD)          // 18432 floats per tile, stored [P][D]

// SMEM float offsets
#define TILE0  0                 // test  tile [36][512]
#define TILE1  TILE_F            // train tile [36][512]
#define MEANO  (2*TILE_F)        // means [2][512]
#define FUSEO  (MEANO + 2*DD)    // fused vectors [2][512]
#define SCO    (FUSEO + 2*DD)    // selection scores [2][36]
#define NNO    (SCO + 72)        // per-position norms [2][36]
#define WWO    (NNO + 72)        // fuse weights [2][36]
#define REDO   (WWO + 72)        // reduction scratch [96]
#define SMEMF  (REDO + 96)
#define SMEMB  (SMEMF * 4)       // ~153.3 KB -> 1 CTA/SM, 1024 thr

__device__ __forceinline__ float warp_sum(float v) {
#pragma unroll
    for (int o = 16; o > 0; o >>= 1) v += __shfl_down_sync(0xffffffffu, v, o);
    return v;
}
__device__ __forceinline__ float dot4(float4 a, float4 b) {
    return a.x*b.x + a.y*b.y + a.z*b.z + a.w*b.w;
}

__global__ __launch_bounds__(NT, 1)
void fused_region_score_pipe(const float* __restrict__ ftrain,
                             const float* __restrict__ ftest,
                             const int*   __restrict__ Kp,
                             float* __restrict__ out,
                             int groups, int halfOut)
{
    extern __shared__ float sm[];
    float* red = sm + REDO;

    const int tid  = threadIdx.x;
    const int lane = tid & 31;
    const int wid  = tid >> 5;
    const int half = tid >> 9;          // 0 = test tensor, 1 = train tensor
    const int d    = tid & 511;
    const int K    = Kp[0];
    const int step = gridDim.x;

    const float* base = half ? ftrain : ftest;
    float* tile = sm + (half ? TILE1 : TILE0);

    // ---- prologue: prefetch first group's row into registers -------------
    float4 pre[9];
    {
        int g0 = min(blockIdx.x, groups - 1);
        const float4* s4 = (const float4*)(base + (size_t)g0 * TILE_F) + d * 9;
#pragma unroll
        for (int k = 0; k < 9; k++) pre[k] = s4[k];
    }

    for (int g = blockIdx.x; g < groups; g += step) {
        // ---- transpose-store tile, compute spatial mean in registers -----
        float s = 0.f;
#pragma unroll
        for (int k = 0; k < 9; k++) {
            tile[(4*k+0)*DD + d] = pre[k].x;
            tile[(4*k+1)*DD + d] = pre[k].y;
            tile[(4*k+2)*DD + d] = pre[k].z;
            tile[(4*k+3)*DD + d] = pre[k].w;
            s += pre[k].x + pre[k].y + pre[k].z + pre[k].w;
        }
        const float m = s * (1.0f / (float)PP);
        sm[MEANO + half*DD + d] = m;
        __syncthreads();                               // sync1: tile+means ready

        // ---- prefetch next group (overlaps all compute below) ------------
        {
            int gn = min(g + step, groups - 1);
            const float4* s4 = (const float4*)(base + (size_t)gn * TILE_F) + d * 9;
#pragma unroll
            for (int k = 0; k < 9; k++) pre[k] = s4[k];
        }

        // ---- stage A partials: global mean-score terms (threads 0..511) --
        if (half == 0) {
            float mt = sm[MEANO + d], mr = sm[MEANO + DD + d];
            float a = warp_sum(mt * mr);
            float b = warp_sum(mt * mt);
            float c = warp_sum(mr * mr);
            if (lane == 0) { red[wid] = a; red[32 + wid] = b; red[64 + wid] = c; }
        }

        // ---- stage B: per-position norm + selection score -----------------
        // 72 jobs (tensor,p); warp w: jobs w, w+32, and w+64 for w<8
        {
            const float4* t4 = (const float4*)sm;   // tiles at float4 granularity
#pragma unroll
            for (int r = 0; r < 3; r++) {
                int j = wid + 32 * r;
                if (r == 2 && wid >= 8) break;
                int tens = j / PP;                   // 0: test rows, 1: train rows
                int p    = j - tens * PP;
                const float4* row = t4 + tens * (TILE_F/4) + p * (DD/4);
                const float4* mo  = (const float4*)(sm + MEANO + (1 - tens) * DD);
                float a2 = 0.f, ta = 0.f;
#pragma unroll
                for (int i = 0; i < 4; i++) {
                    int idx = lane + 32 * i;
                    float4 a = row[idx];
                    float4 mm = mo[idx];
                    a2 += dot4(a, a);
                    ta += dot4(a, mm);
                }
                a2 = warp_sum(a2);
                ta = warp_sum(ta);
                if (lane == 0) {
                    float n = fmaxf(sqrtf(a2), EPSN);
                    sm[NNO + j] = n;
                    sm[SCO + j] = ta / n;            // positive factors cancel in ranking
                }
            }
        }
        __syncthreads();                             // sync2: SC/NN + stage-A red ready

        // ---- stage A final: global score ----------------------------------
        if (wid == 0) {
            float a = (lane < 16) ? red[lane]      : 0.f;
            float b = (lane < 16) ? red[32 + lane] : 0.f;
            float c = (lane < 16) ? red[64 + lane] : 0.f;
            a = warp_sum(a); b = warp_sum(b); c = warp_sum(c);
            if (lane == 0) {
                float den = fmaxf(sqrtf(b), EPSN) * fmaxf(sqrtf(c), EPSN);
                out[g] = SCALE_CLS * a / den;
            }
        }

        // ---- stage C: top-K via rank counting (72 threads) ----------------
        if (tid < 72) {
            int tens = tid / PP;
            int p    = tid - tens * PP;
            int b0   = tens * PP;
            float sv = sm[SCO + tid];
            int rank = 0;
#pragma unroll
            for (int q = 0; q < PP; q++) {
                float o = sm[SCO + b0 + q];
                rank += (o > sv) || (o == sv && q < p);  // lower index wins ties
            }
            sm[WWO + tid] = (rank < K) ? (1.0f / sm[NNO + tid]) : 0.0f;
        }
        __syncthreads();                             // sync3: weights ready

        // ---- stage D: fused vector per (tensor,d) --------------------------
        float u = 0.f;
        {
            const float* w = sm + WWO + half * PP;
#pragma unroll
            for (int p = 0; p < PP; p++)
                u += tile[p * DD + d] * w[p];
        }
        sm[FUSEO + half * DD + d] = u;
        __syncthreads();                             // sync4: fused vecs ready, tile free

        // ---- final score reductions (threads 0..511) -----------------------
        if (half == 0) {
            float ut = u;                            // own fused (test)
            float vt = sm[FUSEO + DD + d];           // train fused
            float a = warp_sum(ut * vt);
            float b = warp_sum(ut * ut);
            float c = warp_sum(vt * vt);
            if (lane == 0) { red[wid] = a; red[32 + wid] = b; red[64 + wid] = c; }
        }
        __syncthreads();                             // sync5: red ready (also tile-WAR)

        if (wid == 0) {
            float a = (lane < 16) ? red[lane]      : 0.f;
            float b = (lane < 16) ? red[32 + lane] : 0.f;
            float c = (lane < 16) ? red[64 + lane] : 0.f;
            a = warp_sum(a); b = warp_sum(b); c = warp_sum(c);
            if (lane == 0) {
                float den = fmaxf(sqrtf(b), EPSN) * fmaxf(sqrtf(c), EPSN);
                out[halfOut + g] = SCALE_CLS * a / den;
            }
        }
        __syncthreads();                             // sync6: red safe for next group
    }
}

extern "C" void kernel_launch(void* const* d_in, const int* in_sizes, int n_in,
                              void* d_out, int out_size)
{
    const float* ftrain = (const float*)d_in[0];
    const float* ftest  = (const float*)d_in[1];
    const int*   Kp     = (const int*)d_in[2];
    float* out = (float*)d_out;

    const int groups  = in_sizes[0] / (DD * PP);   // 1500
    const int halfOut = out_size / 2;              // 1500

    cudaFuncSetAttribute(fused_region_score_pipe,
                         cudaFuncAttributeMaxDynamicSharedMemorySize, SMEMB);
    fused_region_score_pipe<<<148, NT, SMEMB>>>(ftrain, ftest, Kp, out,
                                                groups, halfOut);
}